// round 4
// baseline (speedup 1.0000x reference)
#include <cuda_runtime.h>
#include <math.h>

// Problem constants
#define BB 4096
#define PP 16
#define DD 512
#define FF 2048
#define EE 8

// -------- scratch (device globals; no allocations) --------
__device__ int   g_counts[EE];
__device__ int   g_rows[EE * BB];
__device__ float g_gates[EE * BB];

// -------- zero the per-expert counters --------
__global__ void zero_counts_kernel() {
    if (threadIdx.x < EE) g_counts[threadIdx.x] = 0;
}

// -------- router: noisy top-2 + 2-way softmax, scatter to expert lists --------
__global__ void router_kernel(const float* __restrict__ aff,
                              const float* __restrict__ noise) {
    int b = blockIdx.x * blockDim.x + threadIdx.x;
    if (b >= BB) return;

    float v[EE];
#pragma unroll
    for (int e = 0; e < EE; ++e) {
        float a  = aff[b * EE + e];
        // stable softplus = logaddexp(a, 0)
        float sp = (a > 0.f) ? (a + log1pf(expf(-a))) : log1pf(expf(a));
        v[e] = a + noise[b * EE + e] * sp;
    }

    // top-1 (first max on ties, matching jax top_k)
    int i0 = 0; float v0 = v[0];
#pragma unroll
    for (int e = 1; e < EE; ++e) if (v[e] > v0) { v0 = v[e]; i0 = e; }
    // top-2
    int i1 = -1; float v1 = -INFINITY;
#pragma unroll
    for (int e = 0; e < EE; ++e) if (e != i0 && v[e] > v1) { v1 = v[e]; i1 = e; }

    // softmax over {v0, v1} (others are -inf -> exactly 0 gate)
    float ex  = expf(v1 - v0);
    float inv = 1.f / (1.f + ex);
    float g0  = inv;
    float g1  = ex * inv;

    int p0 = atomicAdd(&g_counts[i0], 1);
    g_rows[i0 * BB + p0]  = b;
    g_gates[i0 * BB + p0] = g0;
    int p1 = atomicAdd(&g_counts[i1], 1);
    g_rows[i1 * BB + p1]  = b;
    g_gates[i1 * BB + p1] = g1;
}

// -------- fused expert FFN --------
// Per CTA: one expert, 2 gathered b-rows = 32 token-patches, full D output.
// Smem: Xs [32][512] (64KB) | hs [32][128] (16KB) | ws shared stage (64KB)
// Loop over F in blocks of 128:
//   GEMM1 (Xs @ W1-block, W1 staged 64x128) -> gelu -> hs (warp-private rows)
//   GEMM2 (hs @ W2-block, W2 staged 32x512 per sub-chunk) -> acc[32][512] in regs
// Epilogue: atomicAdd(out, gate * (acc + b2))

#define SMEM_FLOATS (32 * 512 + 32 * 128 + 16384)
#define SMEM_BYTES  (SMEM_FLOATS * 4)

__global__ __launch_bounds__(256)
void ffn_kernel(const float* __restrict__ X,
                const float* __restrict__ W1,
                const float* __restrict__ b1,
                const float* __restrict__ W2,
                const float* __restrict__ b2,
                float* __restrict__ out) {
    int e    = blockIdx.y;
    int cnt  = g_counts[e];
    int tile = blockIdx.x;
    if (tile * 2 >= cnt) return;   // uniform across CTA

    int   ent0  = tile * 2;
    int   b0    = g_rows[e * BB + ent0];
    float gate0 = g_gates[e * BB + ent0];
    int   b1i   = b0;
    float gate1 = 0.f;               // duplicate row, zero gate -> adds exactly 0
    if (ent0 + 1 < cnt) {
        b1i   = g_rows[e * BB + ent0 + 1];
        gate1 = g_gates[e * BB + ent0 + 1];
    }

    extern __shared__ float sm[];
    float* Xs = sm;                  // [32][512]
    float* hs = sm + 32 * 512;       // [32][128]
    float* ws = hs + 32 * 128;       // [64][128] for W1 / [32][512] for W2

    int tid = threadIdx.x;

    // stage X (fp32, coalesced float4)
    const float* xp0 = X + (size_t)b0  * PP * DD;
    const float* xp1 = X + (size_t)b1i * PP * DD;
    for (int i = tid; i < (32 * 512) / 4; i += 256) {
        int idx = i * 4;
        int tok = idx >> 9, d = idx & 511;
        const float* src = (tok < 16) ? (xp0 + tok * DD + d)
                                      : (xp1 + (tok - 16) * DD + d);
        *(float4*)(Xs + idx) = *(const float4*)src;
    }

    const float* W1e = W1 + (size_t)e * DD * FF;
    const float* W2e = W2 + (size_t)e * FF * DD;
    const float* b1e = b1 + e * FF;
    const float* b2e = b2 + e * DD;

    int tg = (tid >> 5) * 4;   // token base (warp-major): 0..28
    int fc = (tid & 31) * 4;   // f-col base within 128-block
    int dq = (tid & 31) * 4;   // d-col base for GEMM2 (plus 128*k)

    float acc[4][16];
#pragma unroll
    for (int i = 0; i < 4; ++i)
#pragma unroll
        for (int j = 0; j < 16; ++j) acc[i][j] = 0.f;

    for (int fb = 0; fb < FF; fb += 128) {
        // ---- GEMM1: a1[tok 4][f 4] = Xs[32,512] @ W1[:, fb:fb+128] ----
        float a1[4][4];
#pragma unroll
        for (int i = 0; i < 4; ++i)
#pragma unroll
            for (int j = 0; j < 4; ++j) a1[i][j] = 0.f;

        for (int dc = 0; dc < DD; dc += 64) {
            __syncthreads();  // prior ws users done (also orders Xs load on 1st iter)
            for (int i = tid; i < (64 * 128) / 4; i += 256) {
                int idx = i * 4; int r = idx >> 7, c = idx & 127;
                *(float4*)(ws + idx) =
                    *(const float4*)(W1e + (size_t)(dc + r) * FF + fb + c);
            }
            __syncthreads();

            const float* xr0 = Xs + (tg + 0) * 512 + dc;
            const float* xr1 = Xs + (tg + 1) * 512 + dc;
            const float* xr2 = Xs + (tg + 2) * 512 + dc;
            const float* xr3 = Xs + (tg + 3) * 512 + dc;
#pragma unroll 4
            for (int d = 0; d < 64; ++d) {
                float4 w = *(const float4*)(ws + d * 128 + fc);  // LDS.128, conflict-free
                float x0 = xr0[d], x1 = xr1[d], x2 = xr2[d], x3 = xr3[d];  // broadcast
                a1[0][0] += x0 * w.x; a1[0][1] += x0 * w.y; a1[0][2] += x0 * w.z; a1[0][3] += x0 * w.w;
                a1[1][0] += x1 * w.x; a1[1][1] += x1 * w.y; a1[1][2] += x1 * w.z; a1[1][3] += x1 * w.w;
                a1[2][0] += x2 * w.x; a1[2][1] += x2 * w.y; a1[2][2] += x2 * w.z; a1[2][3] += x2 * w.w;
                a1[3][0] += x3 * w.x; a1[3][1] += x3 * w.y; a1[3][2] += x3 * w.z; a1[3][3] += x3 * w.w;
            }
        }

        // ---- bias + tanh-gelu (jax default approximate=True), store to hs ----
        // hs rows tg..tg+3 are written and later read only by this warp.
#pragma unroll
        for (int i = 0; i < 4; ++i)
#pragma unroll
            for (int j = 0; j < 4; ++j) {
                float t = a1[i][j] + b1e[fb + fc + j];
                float c = t + 0.044715f * t * t * t;
                float g = 0.5f * t * (1.f + tanhf(0.7978845608028654f * c));
                hs[(tg + i) * 128 + fc + j] = g;
            }

        // ---- GEMM2: acc[32,512] += hs[32,128-block] @ W2[fb-block, :] ----
        for (int fs = 0; fs < 128; fs += 32) {
            __syncthreads();  // ws reuse; also orders hs writes before cross-lane reads
            for (int i = tid; i < (32 * 512) / 4; i += 256) {
                int idx = i * 4; int r = idx >> 9, c = idx & 511;
                *(float4*)(ws + idx) =
                    *(const float4*)(W2e + (size_t)(fb + fs + r) * DD + c);
            }
            __syncthreads();

#pragma unroll 2
            for (int f = 0; f < 32; ++f) {
                const float* wr = ws + f * 512 + dq;
                float h0 = hs[(tg + 0) * 128 + fs + f];
                float h1 = hs[(tg + 1) * 128 + fs + f];
                float h2 = hs[(tg + 2) * 128 + fs + f];
                float h3 = hs[(tg + 3) * 128 + fs + f];
#pragma unroll
                for (int k = 0; k < 4; ++k) {
                    float4 w = *(const float4*)(wr + 128 * k);   // LDS.128, conflict-free
                    acc[0][k * 4 + 0] += h0 * w.x; acc[0][k * 4 + 1] += h0 * w.y;
                    acc[0][k * 4 + 2] += h0 * w.z; acc[0][k * 4 + 3] += h0 * w.w;
                    acc[1][k * 4 + 0] += h1 * w.x; acc[1][k * 4 + 1] += h1 * w.y;
                    acc[1][k * 4 + 2] += h1 * w.z; acc[1][k * 4 + 3] += h1 * w.w;
                    acc[2][k * 4 + 0] += h2 * w.x; acc[2][k * 4 + 1] += h2 * w.y;
                    acc[2][k * 4 + 2] += h2 * w.z; acc[2][k * 4 + 3] += h2 * w.w;
                    acc[3][k * 4 + 0] += h3 * w.x; acc[3][k * 4 + 1] += h3 * w.y;
                    acc[3][k * 4 + 2] += h3 * w.z; acc[3][k * 4 + 3] += h3 * w.w;
                }
            }
        }
    }

    // ---- epilogue: out += gate * (acc + b2) ----
#pragma unroll
    for (int i = 0; i < 4; ++i) {
        int tok = tg + i;
        float g  = (tok < 16) ? gate0 : gate1;
        int   bb = (tok < 16) ? b0 : b1i;
        int   p  = tok & 15;
        float* op = out + ((size_t)bb * PP + p) * DD;
#pragma unroll
        for (int k = 0; k < 4; ++k)
#pragma unroll
            for (int j = 0; j < 4; ++j) {
                int d = dq + 128 * k + j;
                atomicAdd(op + d, g * (acc[i][k * 4 + j] + b2e[d]));
            }
    }
}

// -------- launch --------
extern "C" void kernel_launch(void* const* d_in, const int* in_sizes, int n_in,
                              void* d_out, int out_size) {
    const float* patch_x  = (const float*)d_in[0];
    // d_in[1] = patch_embedding (shape-only in reference; unused)
    const float* affinity = (const float*)d_in[2];
    const float* noise    = (const float*)d_in[3];
    const float* W1       = (const float*)d_in[4];
    const float* b1       = (const float*)d_in[5];
    const float* W2       = (const float*)d_in[6];
    const float* b2       = (const float*)d_in[7];
    float* out = (float*)d_out;

    cudaMemsetAsync(out, 0, (size_t)out_size * sizeof(float));
    zero_counts_kernel<<<1, 32>>>();
    router_kernel<<<BB / 256, 256>>>(affinity, noise);

    cudaFuncSetAttribute(ffn_kernel,
                         cudaFuncAttributeMaxDynamicSharedMemorySize, SMEM_BYTES);
    dim3 grid(BB / 2, EE);   // covers worst case (all rows on one expert)
    ffn_kernel<<<grid, 256, SMEM_BYTES>>>(patch_x, W1, b1, W2, b2, out);
}

// round 5
// speedup vs baseline: 8.5954x; 8.5954x over previous
#include <cuda_runtime.h>
#include <cuda_fp16.h>
#include <mma.h>
#include <cstdint>
#include <math.h>
using namespace nvcuda;

#define BB 4096
#define PP 16
#define DD 512
#define FF 2048
#define EE 8
#define MAXTILES 1032
#define MAXSLOTS (MAXTILES * 8)

// ---------------- device scratch (no runtime allocation) ----------------
__device__ int    g_counts[EE];
__device__ int    g_rows[EE * BB];
__device__ float  g_gates[EE * BB];
__device__ int    g_off[EE + 1];
__device__ int    g_binc[BB];
__device__ int    g_inv[BB * 2];
__device__ int    g_srow[MAXSLOTS];
__device__ float  g_sgate[MAXSLOTS];
__device__ int    g_texp[MAXTILES];
__device__ __half g_W1h[(size_t)EE * DD * FF];     // [e][d][f]  (K-major rows for GEMM1 B)
__device__ __half g_W2h[(size_t)EE * FF * DD];     // [e][f][d]  (K-major rows for GEMM2 B)
__device__ __half g_Xg[(size_t)MAXSLOTS * PP * DD];
__device__ __half g_H [(size_t)MAXSLOTS * PP * FF];
__device__ float  g_Y [(size_t)MAXSLOTS * PP * DD];

// ---------------- helpers ----------------
__device__ __forceinline__ uint32_t smem_u32(const void* p) {
    uint32_t a;
    asm("{ .reg .u64 t; cvta.to.shared.u64 t, %1; cvt.u32.u64 %0, t; }" : "=r"(a) : "l"(p));
    return a;
}
__device__ __forceinline__ void cp16(uint32_t dst, const void* src) {
    asm volatile("cp.async.cg.shared.global [%0], [%1], 16;" :: "r"(dst), "l"(src));
}
#define CP_COMMIT() asm volatile("cp.async.commit_group;" ::: "memory")
#define CP_WAIT(n)  asm volatile("cp.async.wait_group %0;" :: "n"(n) : "memory")

__device__ __forceinline__ float gelu_t(float t) {
    float c = t * (1.0f + 0.044715f * t * t);
    float th;
    asm("tanh.approx.f32 %0, %1;" : "=f"(th) : "f"(0.7978845608028654f * c));
    return 0.5f * t * (1.0f + th);
}

// ---------------- small kernels ----------------
__global__ void zero_kernel() {
    int i = blockIdx.x * 256 + threadIdx.x;
    if (i < EE) g_counts[i] = 0;
    if (i < BB) g_binc[i] = 0;
}

__global__ void router_kernel(const float* __restrict__ aff,
                              const float* __restrict__ noise) {
    int b = blockIdx.x * blockDim.x + threadIdx.x;
    if (b >= BB) return;
    float v[EE];
#pragma unroll
    for (int e = 0; e < EE; ++e) {
        float a  = aff[b * EE + e];
        float sp = (a > 0.f) ? (a + log1pf(expf(-a))) : log1pf(expf(a));
        v[e] = a + noise[b * EE + e] * sp;
    }
    int i0 = 0; float v0 = v[0];
#pragma unroll
    for (int e = 1; e < EE; ++e) if (v[e] > v0) { v0 = v[e]; i0 = e; }
    int i1 = -1; float v1 = -INFINITY;
#pragma unroll
    for (int e = 0; e < EE; ++e) if (e != i0 && v[e] > v1) { v1 = v[e]; i1 = e; }
    float ex  = expf(v1 - v0);
    float inv = 1.f / (1.f + ex);
    int p0 = atomicAdd(&g_counts[i0], 1);
    g_rows[i0 * BB + p0]  = b;
    g_gates[i0 * BB + p0] = inv;
    int p1 = atomicAdd(&g_counts[i1], 1);
    g_rows[i1 * BB + p1]  = b;
    g_gates[i1 * BB + p1] = ex * inv;
}

__global__ void offsets_kernel() {
    int off = 0;
    for (int e = 0; e < EE; ++e) { g_off[e] = off; off += (g_counts[e] + 7) & ~7; }
    g_off[EE] = off;
}

__global__ void schedule_kernel() {
    int e   = blockIdx.x;
    int cnt = g_counts[e];
    int pad = (cnt + 7) & ~7;
    int off = g_off[e];
    for (int j = threadIdx.x; j < pad; j += 256) {
        int slot = off + j;
        if (j < cnt) {
            int b = g_rows[e * BB + j];
            g_srow[slot]  = b;
            g_sgate[slot] = g_gates[e * BB + j];
            int pos = atomicAdd(&g_binc[b], 1);
            g_inv[b * 2 + pos] = slot;
        } else {
            g_srow[slot]  = g_rows[e * BB];   // duplicate, gate 0, never combined
            g_sgate[slot] = 0.f;
        }
    }
    for (int t = threadIdx.x; t < pad / 8; t += 256) g_texp[off / 8 + t] = e;
}

// fp32 -> fp16 for both weight tensors (no transpose: already K-major rows)
__global__ void convw_kernel(const float* __restrict__ W1, const float* __restrict__ W2) {
    size_t n   = (size_t)EE * DD * FF;             // per tensor
    size_t idx = ((size_t)blockIdx.x * 256 + threadIdx.x) * 4;
    if (idx < n) {
        float4 v = *(const float4*)(W1 + idx);
        g_W1h[idx + 0] = __float2half_rn(v.x); g_W1h[idx + 1] = __float2half_rn(v.y);
        g_W1h[idx + 2] = __float2half_rn(v.z); g_W1h[idx + 3] = __float2half_rn(v.w);
    } else {
        size_t j = idx - n;
        if (j >= n) return;
        float4 v = *(const float4*)(W2 + j);
        g_W2h[j + 0] = __float2half_rn(v.x); g_W2h[j + 1] = __float2half_rn(v.y);
        g_W2h[j + 2] = __float2half_rn(v.z); g_W2h[j + 3] = __float2half_rn(v.w);
    }
}

// gather routed rows -> fp16 slot array
__global__ void gather_kernel(const float* __restrict__ X) {
    int slot = blockIdx.x;
    if (slot * 1 >= g_off[EE]) return;
    int b = g_srow[slot];
    const float4* src = (const float4*)(X + (size_t)b * PP * DD);
    __half2* dst = (__half2*)(g_Xg + (size_t)slot * PP * DD);
    for (int i = threadIdx.x; i < PP * DD / 4; i += 256) {
        float4 v = src[i];
        dst[i * 2 + 0] = __floats2half2_rn(v.x, v.y);
        dst[i * 2 + 1] = __floats2half2_rn(v.z, v.w);
    }
}

// ---------------- wmma GEMM passes ----------------
// CTA: M=128 (one tile = 8 slots), N=64 chunk, K in steps of 64, cp.async 2-stage.
// smem: A[2][128][72] half + B[2][64][72] half = 55296 B; epilogue overlays float C[128][68].
#define LDH 72
#define LDC 68
#define SMEM_BYTES 55296

template <int KDIM, int NDIM, int PASS>
__global__ __launch_bounds__(256)
void gemm_pass(const float* __restrict__ bias) {
    int tile = blockIdx.x;
    if (tile * 8 >= g_off[EE]) return;
    int e  = g_texp[tile];
    int nb = blockIdx.y * 64;

    extern __shared__ char sm[];
    half* As = (half*)sm;                  // [2][128*LDH]
    half* Bs = As + 2 * 128 * LDH;         // [2][64*LDH]
    uint32_t sA = smem_u32(As), sB = smem_u32(Bs);

    const half* Ag = (PASS == 1) ? (g_Xg + (size_t)tile * 128 * KDIM)
                                 : (g_H  + (size_t)tile * 128 * KDIM);
    const half* Bg = (PASS == 1) ? (g_W1h + (size_t)e * DD * FF)
                                 : (g_W2h + (size_t)e * FF * DD);
    const float* be = bias + e * NDIM;

    int tid = threadIdx.x;
    int wid = tid >> 5;
    int wm  = (wid >> 1) * 32;   // warp M base
    int wn  = (wid & 1) * 32;    // warp N base

    wmma::fragment<wmma::accumulator, 16, 16, 16, float> c00, c01, c10, c11;
    wmma::fill_fragment(c00, 0.f); wmma::fill_fragment(c01, 0.f);
    wmma::fill_fragment(c10, 0.f); wmma::fill_fragment(c11, 0.f);

    const int KT = KDIM / 64;

    // stage(buf, kt): A 128x64, B 64x64 halves via cp.async 16B
    auto stage = [&](int buf, int kt) {
        int k0 = kt * 64;
        uint32_t a0 = sA + (uint32_t)buf * (128 * LDH * 2);
        uint32_t b0 = sB + (uint32_t)buf * (64 * LDH * 2);
#pragma unroll
        for (int i = 0; i < 4; ++i) {               // 1024 float4 for A
            int idx = tid + i * 256;
            int r = idx >> 3, c = (idx & 7) << 3;
            cp16(a0 + (uint32_t)(r * LDH + c) * 2, Ag + (size_t)r * KDIM + k0 + c);
        }
#pragma unroll
        for (int i = 0; i < 2; ++i) {               // 512 float4 for B
            int idx = tid + i * 256;
            int r = idx >> 3, c = (idx & 7) << 3;
            cp16(b0 + (uint32_t)(r * LDH + c) * 2, Bg + (size_t)(k0 + r) * NDIM + nb + c);
        }
    };

    stage(0, 0);
    CP_COMMIT();
    for (int kt = 0; kt < KT; ++kt) {
        if (kt + 1 < KT) { stage((kt + 1) & 1, kt + 1); CP_COMMIT(); CP_WAIT(1); }
        else             { CP_WAIT(0); }
        __syncthreads();

        half* A = As + ((kt & 1) * 128 + wm) * LDH;
        half* B = Bs + (kt & 1) * 64 * LDH;
#pragma unroll
        for (int kk = 0; kk < 64; kk += 16) {
            wmma::fragment<wmma::matrix_a, 16, 16, 16, half, wmma::row_major> a0f, a1f;
            wmma::fragment<wmma::matrix_b, 16, 16, 16, half, wmma::row_major> b0f, b1f;
            wmma::load_matrix_sync(a0f, A + kk, LDH);
            wmma::load_matrix_sync(a1f, A + 16 * LDH + kk, LDH);
            wmma::load_matrix_sync(b0f, B + kk * LDH + wn, LDH);
            wmma::load_matrix_sync(b1f, B + kk * LDH + wn + 16, LDH);
            wmma::mma_sync(c00, a0f, b0f, c00);
            wmma::mma_sync(c01, a0f, b1f, c01);
            wmma::mma_sync(c10, a1f, b0f, c10);
            wmma::mma_sync(c11, a1f, b1f, c11);
        }
        __syncthreads();
    }

    // epilogue: overlay float C[128][68] on smem
    float* Cs = (float*)sm;
    wmma::store_matrix_sync(Cs + (wm +  0) * LDC + wn,      c00, LDC, wmma::mem_row_major);
    wmma::store_matrix_sync(Cs + (wm +  0) * LDC + wn + 16, c01, LDC, wmma::mem_row_major);
    wmma::store_matrix_sync(Cs + (wm + 16) * LDC + wn,      c10, LDC, wmma::mem_row_major);
    wmma::store_matrix_sync(Cs + (wm + 16) * LDC + wn + 16, c11, LDC, wmma::mem_row_major);
    __syncthreads();

    if (PASS == 1) {
        for (int i = tid; i < 128 * 64; i += 256) {
            int m = i >> 6, n = i & 63;
            float t = Cs[m * LDC + n] + be[nb + n];
            g_H[((size_t)(tile * 128 + m)) * FF + nb + n] = __float2half_rn(gelu_t(t));
        }
    } else {
        for (int i = tid; i < 128 * 64; i += 256) {
            int m = i >> 6, n = i & 63;
            int slot = tile * 8 + (m >> 4);
            float y = (Cs[m * LDC + n] + be[nb + n]) * g_sgate[slot];
            g_Y[((size_t)(tile * 128 + m)) * DD + nb + n] = y;
        }
    }
}

// out[b] = Y[slot0(b)] + Y[slot1(b)]  (bitwise-commutative -> deterministic)
__global__ void combine_kernel(float* __restrict__ out) {
    int b  = blockIdx.x;
    int s0 = g_inv[2 * b], s1 = g_inv[2 * b + 1];
    const float4* y0 = (const float4*)(g_Y + (size_t)s0 * PP * DD);
    const float4* y1 = (const float4*)(g_Y + (size_t)s1 * PP * DD);
    float4* o = (float4*)(out + (size_t)b * PP * DD);
    for (int i = threadIdx.x; i < PP * DD / 4; i += 256) {
        float4 a = y0[i], c = y1[i];
        o[i] = make_float4(a.x + c.x, a.y + c.y, a.z + c.z, a.w + c.w);
    }
}

// ---------------- launch ----------------
extern "C" void kernel_launch(void* const* d_in, const int* in_sizes, int n_in,
                              void* d_out, int out_size) {
    const float* patch_x  = (const float*)d_in[0];
    const float* affinity = (const float*)d_in[2];
    const float* noise    = (const float*)d_in[3];
    const float* W1       = (const float*)d_in[4];
    const float* b1       = (const float*)d_in[5];
    const float* W2       = (const float*)d_in[6];
    const float* b2       = (const float*)d_in[7];
    float* out = (float*)d_out;

    zero_kernel<<<16, 256>>>();
    router_kernel<<<BB / 256, 256>>>(affinity, noise);
    offsets_kernel<<<1, 1>>>();
    schedule_kernel<<<EE, 256>>>();

    size_t wn = (size_t)EE * DD * FF;                       // 8.4M per tensor
    int convBlocks = (int)((2 * wn / 4 + 255) / 256);
    convw_kernel<<<convBlocks, 256>>>(W1, W2);
    gather_kernel<<<MAXSLOTS, 256>>>(patch_x);

    cudaFuncSetAttribute(gemm_pass<DD, FF, 1>,
                         cudaFuncAttributeMaxDynamicSharedMemorySize, SMEM_BYTES);
    cudaFuncSetAttribute(gemm_pass<FF, DD, 2>,
                         cudaFuncAttributeMaxDynamicSharedMemorySize, SMEM_BYTES);

    dim3 g1(MAXTILES, FF / 64);   // K=512,  N=2048
    gemm_pass<DD, FF, 1><<<g1, 256, SMEM_BYTES>>>(b1);
    dim3 g2(MAXTILES, DD / 64);   // K=2048, N=512
    gemm_pass<FF, DD, 2><<<g2, 256, SMEM_BYTES>>>(b2);

    combine_kernel<<<BB, 256>>>(out);
}

// round 7
// speedup vs baseline: 8.7238x; 1.0149x over previous
#include <cuda_runtime.h>
#include <cuda_fp16.h>
#include <mma.h>
#include <cstdint>
#include <math.h>
using namespace nvcuda;

#define BB 4096
#define PP 16
#define DD 512
#define FF 2048
#define EE 8
#define MAXTILES 1032
#define MAXSLOTS (MAXTILES * 8)

// ---------------- device scratch (no runtime allocation) ----------------
__device__ int    g_counts[EE];
__device__ int    g_rows[EE * BB];
__device__ float  g_gates[EE * BB];
__device__ int    g_off[EE + 1];
__device__ int    g_binc[BB];
__device__ int    g_inv[BB * 2];
__device__ int    g_srow[MAXSLOTS];
__device__ float  g_sgate[MAXSLOTS];
__device__ int    g_texp[MAXTILES];
__device__ __half g_W1h[(size_t)EE * DD * FF];   // [e][d][f]
__device__ __half g_W2h[(size_t)EE * FF * DD];   // [e][f][d]
__device__ __half g_Xg[(size_t)MAXSLOTS * PP * DD];
__device__ __half g_H [(size_t)MAXSLOTS * PP * FF];
__device__ float  g_Y [(size_t)MAXSLOTS * PP * DD];

// ---------------- helpers ----------------
__device__ __forceinline__ uint32_t smem_u32(const void* p) {
    uint32_t a;
    asm("{ .reg .u64 t; cvta.to.shared.u64 t, %1; cvt.u32.u64 %0, t; }" : "=r"(a) : "l"(p));
    return a;
}
__device__ __forceinline__ void cp16(uint32_t dst, const void* src) {
    asm volatile("cp.async.cg.shared.global [%0], [%1], 16;" :: "r"(dst), "l"(src));
}
#define CP_COMMIT() asm volatile("cp.async.commit_group;" ::: "memory")
#define CP_WAIT(n)  asm volatile("cp.async.wait_group %0;" :: "n"(n) : "memory")

__device__ __forceinline__ float gelu_t(float t) {
    float c = t * (1.0f + 0.044715f * t * t);
    float th;
    asm("tanh.approx.f32 %0, %1;" : "=f"(th) : "f"(0.7978845608028654f * c));
    return 0.5f * t * (1.0f + th);
}

// ---------------- small kernels ----------------
__global__ void zero_kernel() {
    int i = blockIdx.x * 256 + threadIdx.x;
    if (i < EE) g_counts[i] = 0;
    if (i < BB) g_binc[i] = 0;
}

__global__ void router_kernel(const float* __restrict__ aff,
                              const float* __restrict__ noise) {
    int b = blockIdx.x * blockDim.x + threadIdx.x;
    if (b >= BB) return;
    float v[EE];
#pragma unroll
    for (int e = 0; e < EE; ++e) {
        float a  = aff[b * EE + e];
        float sp = (a > 0.f) ? (a + log1pf(expf(-a))) : log1pf(expf(a));
        v[e] = a + noise[b * EE + e] * sp;
    }
    int i0 = 0; float v0 = v[0];
#pragma unroll
    for (int e = 1; e < EE; ++e) if (v[e] > v0) { v0 = v[e]; i0 = e; }
    int i1 = -1; float v1 = -INFINITY;
#pragma unroll
    for (int e = 0; e < EE; ++e) if (e != i0 && v[e] > v1) { v1 = v[e]; i1 = e; }
    float ex  = expf(v1 - v0);
    float inv = 1.f / (1.f + ex);
    int p0 = atomicAdd(&g_counts[i0], 1);
    g_rows[i0 * BB + p0]  = b;
    g_gates[i0 * BB + p0] = inv;
    int p1 = atomicAdd(&g_counts[i1], 1);
    g_rows[i1 * BB + p1]  = b;
    g_gates[i1 * BB + p1] = ex * inv;
}

__global__ void offsets_kernel() {
    int off = 0;
    for (int e = 0; e < EE; ++e) { g_off[e] = off; off += (g_counts[e] + 7) & ~7; }
    g_off[EE] = off;
}

__global__ void schedule_kernel() {
    int e   = blockIdx.x;
    int cnt = g_counts[e];
    int pad = (cnt + 7) & ~7;
    int off = g_off[e];
    for (int j = threadIdx.x; j < pad; j += 256) {
        int slot = off + j;
        if (j < cnt) {
            int b = g_rows[e * BB + j];
            g_srow[slot]  = b;
            g_sgate[slot] = g_gates[e * BB + j];
            int pos = atomicAdd(&g_binc[b], 1);
            g_inv[b * 2 + pos] = slot;
        } else {
            g_srow[slot]  = g_rows[e * BB];
            g_sgate[slot] = 0.f;
        }
    }
    for (int t = threadIdx.x; t < pad / 8; t += 256) g_texp[off / 8 + t] = e;
}

__global__ void convw_kernel(const float* __restrict__ W1, const float* __restrict__ W2) {
    size_t n   = (size_t)EE * DD * FF;
    size_t idx = ((size_t)blockIdx.x * 256 + threadIdx.x) * 4;
    if (idx < n) {
        float4 v = *(const float4*)(W1 + idx);
        g_W1h[idx + 0] = __float2half_rn(v.x); g_W1h[idx + 1] = __float2half_rn(v.y);
        g_W1h[idx + 2] = __float2half_rn(v.z); g_W1h[idx + 3] = __float2half_rn(v.w);
    } else {
        size_t j = idx - n;
        if (j >= n) return;
        float4 v = *(const float4*)(W2 + j);
        g_W2h[j + 0] = __float2half_rn(v.x); g_W2h[j + 1] = __float2half_rn(v.y);
        g_W2h[j + 2] = __float2half_rn(v.z); g_W2h[j + 3] = __float2half_rn(v.w);
    }
}

__global__ void gather_kernel(const float* __restrict__ X) {
    int slot = blockIdx.x;
    if (slot >= g_off[EE]) return;
    int b = g_srow[slot];
    const float4* src = (const float4*)(X + (size_t)b * PP * DD);
    __half2* dst = (__half2*)(g_Xg + (size_t)slot * PP * DD);
    for (int i = threadIdx.x; i < PP * DD / 4; i += 256) {
        float4 v = src[i];
        dst[i * 2 + 0] = __floats2half2_rn(v.x, v.y);
        dst[i * 2 + 1] = __floats2half2_rn(v.z, v.w);
    }
}

// ---------------- GEMM pass 1: H = gelu(X @ W1 + b1), A-resident ----------------
// smem: A[128][520]h = 133120 B | B[2][64][136]h = 34816 B | C[128][68]f = 34816 B
#define LDA1 520
#define LDB  136
#define LDC  68
#define SM1_B 133120
#define SM1_C 167936
#define SM1_BYTES 202752

__global__ __launch_bounds__(256)
void gemm1_kernel(const float* __restrict__ bias) {
    int tile = blockIdx.x;
    if (tile * 8 >= g_off[EE]) return;
    int e = g_texp[tile];

    extern __shared__ char sm[];
    half*  A  = (half*)sm;
    half*  Bs = (half*)(sm + SM1_B);
    float* C  = (float*)(sm + SM1_C);
    uint32_t sA = smem_u32(A), sB = smem_u32(Bs);

    const half* Ag = g_Xg + (size_t)tile * 128 * DD;
    const half* Bg = g_W1h + (size_t)e * DD * FF;
    const float* be = bias + e * FF;

    int tid = threadIdx.x, wid = tid >> 5;
    int wm = (wid >> 1) * 32, wn = (wid & 1) * 64;

    // resident A: 128x512 fp16 = 8192 16B chunks  (R5 bug: was 16 iters = half tile)
#pragma unroll
    for (int i = 0; i < 32; ++i) {
        int idx = i * 256 + tid;
        int r = idx >> 6, c = (idx & 63) << 3;
        cp16(sA + (uint32_t)(r * LDA1 + c) * 2, Ag + r * DD + c);
    }

    // B chunk q (0..127): nb=(q>>3)*128, k0=(q&7)*64, 64 rows x 128 cols
    auto stageB = [&](int q) {
        uint32_t dst = sB + (uint32_t)(q & 1) * (64 * LDB * 2);
        int nb = (q >> 3) << 7, k0 = (q & 7) << 6;
#pragma unroll
        for (int i = 0; i < 4; ++i) {
            int idx = i * 256 + tid;
            int r = idx >> 4, c = (idx & 15) << 3;
            cp16(dst + (uint32_t)(r * LDB + c) * 2, Bg + (size_t)(k0 + r) * FF + nb + c);
        }
    };
    stageB(0);
    CP_COMMIT();   // group 0: A + B0

    wmma::fragment<wmma::accumulator, 16, 16, 16, float> acc[2][4];

    for (int q = 0; q < 128; ++q) {
        int kc = q & 7;
        if (kc == 0) {
#pragma unroll
            for (int i = 0; i < 2; ++i)
#pragma unroll
                for (int j = 0; j < 4; ++j) wmma::fill_fragment(acc[i][j], 0.f);
        }
        if (q + 1 < 128) { stageB(q + 1); CP_COMMIT(); CP_WAIT(1); }
        else             { CP_WAIT(0); }
        __syncthreads();

        half* Bq = Bs + (q & 1) * (64 * LDB);
        int k0 = kc << 6;
#pragma unroll
        for (int kk = 0; kk < 64; kk += 16) {
            wmma::fragment<wmma::matrix_a, 16, 16, 16, half, wmma::row_major> af[2];
            wmma::fragment<wmma::matrix_b, 16, 16, 16, half, wmma::row_major> bf[4];
            wmma::load_matrix_sync(af[0], A + (wm +  0) * LDA1 + k0 + kk, LDA1);
            wmma::load_matrix_sync(af[1], A + (wm + 16) * LDA1 + k0 + kk, LDA1);
#pragma unroll
            for (int j = 0; j < 4; ++j)
                wmma::load_matrix_sync(bf[j], Bq + kk * LDB + wn + 16 * j, LDB);
#pragma unroll
            for (int i = 0; i < 2; ++i)
#pragma unroll
                for (int j = 0; j < 4; ++j) wmma::mma_sync(acc[i][j], af[i], bf[j], acc[i][j]);
        }
        __syncthreads();   // compute done -> next iter may overwrite other B buf

        if (kc == 7) {
            int nb = (q >> 3) << 7;
#pragma unroll
            for (int p = 0; p < 2; ++p) {   // two N=64 phases through C
                if ((wid & 1) == p) {
#pragma unroll
                    for (int i = 0; i < 2; ++i)
#pragma unroll
                        for (int j = 0; j < 4; ++j)
                            wmma::store_matrix_sync(C + (wm + 16 * i) * LDC + 16 * j,
                                                    acc[i][j], LDC, wmma::mem_row_major);
                }
                __syncthreads();
                for (int i = tid; i < 128 * 64; i += 256) {
                    int m = i >> 6, n = i & 63;
                    float t = C[m * LDC + n] + be[nb + p * 64 + n];
                    g_H[(size_t)(tile * 128 + m) * FF + nb + p * 64 + n] =
                        __float2half_rn(gelu_t(t));
                }
                __syncthreads();
            }
        }
    }
}

// ---------------- GEMM pass 2: Y = gate*(H @ W2 + b2), streamed K ----------------
// smem: A[2][128][72]h = 36864 B | B[2][64][136]h = 34816 B | C[128][68]f = 34816 B
#define LDA2 72
#define SM2_B 36864
#define SM2_C 71680
#define SM2_BYTES 106496

__global__ __launch_bounds__(256)
void gemm2_kernel(const float* __restrict__ bias) {
    int tile = blockIdx.x;
    if (tile * 8 >= g_off[EE]) return;
    int e  = g_texp[tile];
    int nb = blockIdx.y << 7;

    extern __shared__ char sm[];
    half*  As = (half*)sm;
    half*  Bs = (half*)(sm + SM2_B);
    float* C  = (float*)(sm + SM2_C);
    uint32_t sA = smem_u32(As), sB = smem_u32(Bs);

    const half* Ag = g_H  + (size_t)tile * 128 * FF;
    const half* Bg = g_W2h + (size_t)e * FF * DD;
    const float* be = bias + e * DD;

    int tid = threadIdx.x, wid = tid >> 5;
    int wm = (wid >> 1) * 32, wn = (wid & 1) * 64;

    auto stage = [&](int q) {   // K chunk q (0..31), k0=q*64
        int k0 = q << 6, buf = q & 1;
        uint32_t da = sA + (uint32_t)buf * (128 * LDA2 * 2);
        uint32_t db = sB + (uint32_t)buf * (64 * LDB * 2);
#pragma unroll
        for (int i = 0; i < 4; ++i) {   // A: 128 x 64 = 1024 chunks
            int idx = i * 256 + tid;
            int r = idx >> 3, c = (idx & 7) << 3;
            cp16(da + (uint32_t)(r * LDA2 + c) * 2, Ag + (size_t)r * FF + k0 + c);
        }
#pragma unroll
        for (int i = 0; i < 4; ++i) {   // B: 64 x 128 = 1024 chunks
            int idx = i * 256 + tid;
            int r = idx >> 4, c = (idx & 15) << 3;
            cp16(db + (uint32_t)(r * LDB + c) * 2, Bg + (size_t)(k0 + r) * DD + nb + c);
        }
    };
    stage(0);
    CP_COMMIT();

    wmma::fragment<wmma::accumulator, 16, 16, 16, float> acc[2][4];
#pragma unroll
    for (int i = 0; i < 2; ++i)
#pragma unroll
        for (int j = 0; j < 4; ++j) wmma::fill_fragment(acc[i][j], 0.f);

    for (int q = 0; q < 32; ++q) {
        if (q + 1 < 32) { stage(q + 1); CP_COMMIT(); CP_WAIT(1); }
        else            { CP_WAIT(0); }
        __syncthreads();

        half* Aq = As + (q & 1) * (128 * LDA2);
        half* Bq = Bs + (q & 1) * (64 * LDB);
#pragma unroll
        for (int kk = 0; kk < 64; kk += 16) {
            wmma::fragment<wmma::matrix_a, 16, 16, 16, half, wmma::row_major> af[2];
            wmma::fragment<wmma::matrix_b, 16, 16, 16, half, wmma::row_major> bf[4];
            wmma::load_matrix_sync(af[0], Aq + (wm +  0) * LDA2 + kk, LDA2);
            wmma::load_matrix_sync(af[1], Aq + (wm + 16) * LDA2 + kk, LDA2);
#pragma unroll
            for (int j = 0; j < 4; ++j)
                wmma::load_matrix_sync(bf[j], Bq + kk * LDB + wn + 16 * j, LDB);
#pragma unroll
            for (int i = 0; i < 2; ++i)
#pragma unroll
                for (int j = 0; j < 4; ++j) wmma::mma_sync(acc[i][j], af[i], bf[j], acc[i][j]);
        }
        __syncthreads();
    }

#pragma unroll
    for (int p = 0; p < 2; ++p) {
        if ((wid & 1) == p) {
#pragma unroll
            for (int i = 0; i < 2; ++i)
#pragma unroll
                for (int j = 0; j < 4; ++j)
                    wmma::store_matrix_sync(C + (wm + 16 * i) * LDC + 16 * j,
                                            acc[i][j], LDC, wmma::mem_row_major);
        }
        __syncthreads();
        for (int i = tid; i < 128 * 64; i += 256) {
            int m = i >> 6, n = i & 63;
            int slot = tile * 8 + (m >> 4);
            float y = (C[m * LDC + n] + be[nb + p * 64 + n]) * g_sgate[slot];
            g_Y[(size_t)(tile * 128 + m) * DD + nb + p * 64 + n] = y;
        }
        __syncthreads();
    }
}

// out[b] = Y[slot0(b)] + Y[slot1(b)]
__global__ void combine_kernel(float* __restrict__ out) {
    int b  = blockIdx.x;
    int s0 = g_inv[2 * b], s1 = g_inv[2 * b + 1];
    const float4* y0 = (const float4*)(g_Y + (size_t)s0 * PP * DD);
    const float4* y1 = (const float4*)(g_Y + (size_t)s1 * PP * DD);
    float4* o = (float4*)(out + (size_t)b * PP * DD);
    for (int i = threadIdx.x; i < PP * DD / 4; i += 256) {
        float4 a = y0[i], c = y1[i];
        o[i] = make_float4(a.x + c.x, a.y + c.y, a.z + c.z, a.w + c.w);
    }
}

// ---------------- launch ----------------
extern "C" void kernel_launch(void* const* d_in, const int* in_sizes, int n_in,
                              void* d_out, int out_size) {
    const float* patch_x  = (const float*)d_in[0];
    const float* affinity = (const float*)d_in[2];
    const float* noise    = (const float*)d_in[3];
    const float* W1       = (const float*)d_in[4];
    const float* b1       = (const float*)d_in[5];
    const float* W2       = (const float*)d_in[6];
    const float* b2       = (const float*)d_in[7];
    float* out = (float*)d_out;

    zero_kernel<<<16, 256>>>();
    router_kernel<<<BB / 256, 256>>>(affinity, noise);
    offsets_kernel<<<1, 1>>>();
    schedule_kernel<<<EE, 256>>>();

    size_t wn = (size_t)EE * DD * FF;
    int convBlocks = (int)((2 * wn / 4 + 255) / 256);
    convw_kernel<<<convBlocks, 256>>>(W1, W2);
    gather_kernel<<<MAXSLOTS, 256>>>(patch_x);

    cudaFuncSetAttribute(gemm1_kernel,
                         cudaFuncAttributeMaxDynamicSharedMemorySize, SM1_BYTES);
    cudaFuncSetAttribute(gemm2_kernel,
                         cudaFuncAttributeMaxDynamicSharedMemorySize, SM2_BYTES);

    gemm1_kernel<<<MAXTILES, 256, SM1_BYTES>>>(b1);
    dim3 g2(MAXTILES, DD / 128);
    gemm2_kernel<<<g2, 256, SM2_BYTES>>>(b2);

    combine_kernel<<<BB, 256>>>(out);
}